// round 5
// baseline (speedup 1.0000x reference)
#include <cuda_runtime.h>
#include <cuda_bf16.h>
#include <cstdint>

#define NUM_E 16
#define D_IN  2048
#define D_OUT 8192
#define T_TOK 8192

// CTA tile 128(M) x 256(N), K-chunk 16. 8 warps = 2(M) x 4(N), warp tile 64x64.
#define BM 128
#define BN 256
#define BK 16
#define NCHUNK (D_IN / BK)   // 128
#define THREADS 256

// smem rows: 16 bf16 = 32B data + 16B pad = 48B stride (conflict-free ldmatrix).
#define ROW_B  48
#define A_HI   0
#define A_LO   (128 * ROW_B)
#define B_HI   (2 * 128 * ROW_B)
#define B_LO   (B_HI + 256 * ROW_B)
#define STAGE_B (B_LO + 256 * ROW_B)      // 36864
#define SMEM_BYTES (2 * STAGE_B)          // 73728

__device__ __forceinline__ uint32_t smem_u32_of(const void* p) {
    uint32_t a;
    asm("{ .reg .u64 t; cvta.to.shared.u64 t, %1; cvt.u32.u64 %0, t; }" : "=r"(a) : "l"(p));
    return a;
}

__device__ __forceinline__ uint32_t pack2(__nv_bfloat16 a, __nv_bfloat16 b) {
    __nv_bfloat162 t = __halves2bfloat162(a, b);
    return *reinterpret_cast<uint32_t*>(&t);
}

__device__ __forceinline__ void sts16(uint32_t addr, const uint32_t* r) {
    asm volatile("st.shared.v4.b32 [%0], {%1, %2, %3, %4};"
                 :: "r"(addr), "r"(r[0]), "r"(r[1]), "r"(r[2]), "r"(r[3]) : "memory");
}

// Split 8 consecutive fp32 into bf16 hi (16B) + residual lo (16B) and store.
__device__ __forceinline__ void split_store8(const float* v, uint32_t hi_addr, uint32_t lo_addr) {
    uint32_t h[4], l[4];
    #pragma unroll
    for (int i = 0; i < 4; i++) {
        __nv_bfloat16 h0 = __float2bfloat16(v[2 * i]);
        __nv_bfloat16 h1 = __float2bfloat16(v[2 * i + 1]);
        __nv_bfloat16 l0 = __float2bfloat16(v[2 * i] - __bfloat162float(h0));
        __nv_bfloat16 l1 = __float2bfloat16(v[2 * i + 1] - __bfloat162float(h1));
        h[i] = pack2(h0, h1);
        l[i] = pack2(l0, l1);
    }
    sts16(hi_addr, h);
    sts16(lo_addr, l);
}

__device__ __forceinline__ void ldsm_x4(uint32_t* r, uint32_t addr) {
    asm volatile("ldmatrix.sync.aligned.m8n8.x4.shared.b16 {%0,%1,%2,%3}, [%4];"
                 : "=r"(r[0]), "=r"(r[1]), "=r"(r[2]), "=r"(r[3]) : "r"(addr));
}

__device__ __forceinline__ void mma_bf16(float* d, const uint32_t* a, uint32_t b0, uint32_t b1) {
    asm volatile(
        "mma.sync.aligned.m16n8k16.row.col.f32.bf16.bf16.f32 "
        "{%0,%1,%2,%3}, {%4,%5,%6,%7}, {%8,%9}, {%0,%1,%2,%3};"
        : "+f"(d[0]), "+f"(d[1]), "+f"(d[2]), "+f"(d[3])
        : "r"(a[0]), "r"(a[1]), "r"(a[2]), "r"(a[3]), "r"(b0), "r"(b1));
}

__global__ __launch_bounds__(THREADS, 1)
void moe_gemm_mma3_kernel(const float* __restrict__ inp,     // [T, D_IN]
                          const float* __restrict__ weight,  // [E, D_OUT, D_IN]
                          const float* __restrict__ bias,    // [E, D_OUT]
                          const int*   __restrict__ cnt,     // [E]
                          float*       __restrict__ out)     // [T, D_OUT]
{
    extern __shared__ char smem[];
    const uint32_t sbase = smem_u32_of(smem);

    const int tid = threadIdx.x;
    const int wid = tid >> 5;
    const int lid = tid & 31;

    const int nBase = blockIdx.x * BN;
    const int mBase = blockIdx.y * BM;

    int e = 0;
    {
        int acc = 0;
        #pragma unroll
        for (int i = 0; i < NUM_E; i++) {
            int c = cnt[i];
            if (mBase >= acc + c) { acc += c; e = i + 1; }
        }
    }
    const float* wptr = weight + (size_t)e * D_OUT * D_IN;

    const int warp_m = (wid >> 2) * 64;
    const int warp_n = (wid & 3) * 64;

    const int a_row = (lid & 7) + ((lid >> 3) & 1) * 8;
    const int a_ks  = ((lid >> 4) & 1) * 8;
    const int b_row = (lid & 7) + ((lid >> 4) & 1) * 8;
    const int b_ks  = ((lid >> 3) & 1) * 8;

    const int arow = tid >> 1;
    const int acol = (tid & 1) * 8;
    const float* aG  = inp  + (size_t)(mBase + arow) * D_IN + acol;
    const float* bG0 = wptr + (size_t)(nBase + arow) * D_IN + acol;
    const float* bG1 = wptr + (size_t)(nBase + 128 + arow) * D_IN + acol;

    const uint32_t a_st  = (uint32_t)(arow * ROW_B + acol * 2);
    const uint32_t b_st0 = a_st;
    const uint32_t b_st1 = (uint32_t)((128 + arow) * ROW_B + acol * 2);

    float d[4][8][4];
    #pragma unroll
    for (int f = 0; f < 4; f++)
        #pragma unroll
        for (int n = 0; n < 8; n++)
            #pragma unroll
            for (int k = 0; k < 4; k++)
                d[f][n][k] = 0.0f;

    float aV[8], bV0[8], bV1[8];

    #pragma unroll
    for (int q = 0; q < 2; q++) {
        *reinterpret_cast<float4*>(aV  + q * 4) = *reinterpret_cast<const float4*>(aG  + q * 4);
        *reinterpret_cast<float4*>(bV0 + q * 4) = *reinterpret_cast<const float4*>(bG0 + q * 4);
        *reinterpret_cast<float4*>(bV1 + q * 4) = *reinterpret_cast<const float4*>(bG1 + q * 4);
    }
    split_store8(aV,  sbase + A_HI + a_st,  sbase + A_LO + a_st);
    split_store8(bV0, sbase + B_HI + b_st0, sbase + B_LO + b_st0);
    split_store8(bV1, sbase + B_HI + b_st1, sbase + B_LO + b_st1);
    __syncthreads();

    for (int i = 0; i < NCHUNK; i++) {
        if (i + 1 < NCHUNK) {
            const int kb = (i + 1) * BK;
            #pragma unroll
            for (int q = 0; q < 2; q++) {
                *reinterpret_cast<float4*>(aV  + q * 4) = *reinterpret_cast<const float4*>(aG  + kb + q * 4);
                *reinterpret_cast<float4*>(bV0 + q * 4) = *reinterpret_cast<const float4*>(bG0 + kb + q * 4);
                *reinterpret_cast<float4*>(bV1 + q * 4) = *reinterpret_cast<const float4*>(bG1 + kb + q * 4);
            }
        }

        const uint32_t cur = sbase + (uint32_t)(i & 1) * STAGE_B;

        uint32_t ah[4][4], al[4][4];
        #pragma unroll
        for (int f = 0; f < 4; f++) {
            uint32_t ro = (uint32_t)((warp_m + f * 16 + a_row) * ROW_B + a_ks * 2);
            ldsm_x4(ah[f], cur + A_HI + ro);
            ldsm_x4(al[f], cur + A_LO + ro);
        }
        #pragma unroll
        for (int nb = 0; nb < 4; nb++) {
            uint32_t bh[4], bl[4];
            uint32_t ro = (uint32_t)((warp_n + nb * 16 + b_row) * ROW_B + b_ks * 2);
            ldsm_x4(bh, cur + B_HI + ro);
            ldsm_x4(bl, cur + B_LO + ro);
            // Term-major issue order: same accumulator reused only every 8 MMAs,
            // covering HMMA RAW latency (the round-3/4 d0,d1 alternation had
            // distance 2 and capped the tensor pipe at ~50%).
            #pragma unroll
            for (int f = 0; f < 4; f++) {           // hi*hi
                mma_bf16(d[f][nb * 2 + 0], ah[f], bh[0], bh[1]);
                mma_bf16(d[f][nb * 2 + 1], ah[f], bh[2], bh[3]);
            }
            #pragma unroll
            for (int f = 0; f < 4; f++) {           // hi*lo
                mma_bf16(d[f][nb * 2 + 0], ah[f], bl[0], bl[1]);
                mma_bf16(d[f][nb * 2 + 1], ah[f], bl[2], bl[3]);
            }
            #pragma unroll
            for (int f = 0; f < 4; f++) {           // lo*hi
                mma_bf16(d[f][nb * 2 + 0], al[f], bh[0], bh[1]);
                mma_bf16(d[f][nb * 2 + 1], al[f], bh[2], bh[3]);
            }
        }

        if (i + 1 < NCHUNK) {
            const uint32_t nxt = sbase + (uint32_t)((i + 1) & 1) * STAGE_B;
            split_store8(aV,  nxt + A_HI + a_st,  nxt + A_LO + a_st);
            split_store8(bV0, nxt + B_HI + b_st0, nxt + B_LO + b_st0);
            split_store8(bV1, nxt + B_HI + b_st1, nxt + B_LO + b_st1);
        }
        __syncthreads();
    }

    const int g  = lid >> 2;
    const int t4 = lid & 3;
    const float* brow = bias + (size_t)e * D_OUT;
    #pragma unroll
    for (int f = 0; f < 4; f++) {
        const int row0 = mBase + warp_m + f * 16 + g;
        #pragma unroll
        for (int nf = 0; nf < 8; nf++) {
            const int col = nBase + warp_n + nf * 8 + t4 * 2;
            float2 bv = *reinterpret_cast<const float2*>(brow + col);
            float2 o0, o1;
            o0.x = d[f][nf][0] + bv.x;
            o0.y = d[f][nf][1] + bv.y;
            o1.x = d[f][nf][2] + bv.x;
            o1.y = d[f][nf][3] + bv.y;
            *reinterpret_cast<float2*>(out + (size_t)row0 * D_OUT + col) = o0;
            *reinterpret_cast<float2*>(out + (size_t)(row0 + 8) * D_OUT + col) = o1;
        }
    }
}

extern "C" void kernel_launch(void* const* d_in, const int* in_sizes, int n_in,
                              void* d_out, int out_size)
{
    const float* inp    = (const float*)d_in[0];
    const float* weight = (const float*)d_in[1];
    const float* bias   = (const float*)d_in[2];
    const int*   cnt    = (const int*)d_in[3];
    float* out = (float*)d_out;

    cudaFuncSetAttribute(moe_gemm_mma3_kernel,
                         cudaFuncAttributeMaxDynamicSharedMemorySize, SMEM_BYTES);

    dim3 grid(D_OUT / BN, T_TOK / BM);   // (32, 64)
    moe_gemm_mma3_kernel<<<grid, THREADS, SMEM_BYTES>>>(inp, weight, bias, cnt, out);
}

// round 6
// speedup vs baseline: 1.2112x; 1.2112x over previous
#include <cuda_runtime.h>
#include <cuda_bf16.h>
#include <cstdint>

#define NUM_E 16
#define D_IN  2048
#define D_OUT 8192
#define T_TOK 8192

// CTA tile 128(M) x 128(N), K-chunk 16. 8 warps = 2(M) x 4(N), warp tile 64x32.
#define BM 128
#define BN 128
#define BK 16
#define NCHUNK (D_IN / BK)   // 128
#define THREADS 256

// smem rows: 16 bf16 = 32B data + 16B pad = 48B stride (conflict-free ldmatrix).
#define ROW_B  48
#define A_HI   0
#define A_LO   (128 * ROW_B)              // 6144
#define B_HI   (2 * 128 * ROW_B)          // 12288
#define B_LO   (3 * 128 * ROW_B)          // 18432
#define STAGE_B (4 * 128 * ROW_B)         // 24576
#define SMEM_BYTES (2 * STAGE_B)          // 49152 per CTA -> 2 CTAs/SM

__device__ __forceinline__ uint32_t smem_u32_of(const void* p) {
    uint32_t a;
    asm("{ .reg .u64 t; cvta.to.shared.u64 t, %1; cvt.u32.u64 %0, t; }" : "=r"(a) : "l"(p));
    return a;
}

__device__ __forceinline__ uint32_t pack2(__nv_bfloat16 a, __nv_bfloat16 b) {
    __nv_bfloat162 t = __halves2bfloat162(a, b);
    return *reinterpret_cast<uint32_t*>(&t);
}

__device__ __forceinline__ void sts16(uint32_t addr, const uint32_t* r) {
    asm volatile("st.shared.v4.b32 [%0], {%1, %2, %3, %4};"
                 :: "r"(addr), "r"(r[0]), "r"(r[1]), "r"(r[2]), "r"(r[3]) : "memory");
}

// Split 8 consecutive fp32 into bf16 hi (16B) + residual lo (16B) and store.
__device__ __forceinline__ void split_store8(const float* v, uint32_t hi_addr, uint32_t lo_addr) {
    uint32_t h[4], l[4];
    #pragma unroll
    for (int i = 0; i < 4; i++) {
        __nv_bfloat16 h0 = __float2bfloat16(v[2 * i]);
        __nv_bfloat16 h1 = __float2bfloat16(v[2 * i + 1]);
        __nv_bfloat16 l0 = __float2bfloat16(v[2 * i] - __bfloat162float(h0));
        __nv_bfloat16 l1 = __float2bfloat16(v[2 * i + 1] - __bfloat162float(h1));
        h[i] = pack2(h0, h1);
        l[i] = pack2(l0, l1);
    }
    sts16(hi_addr, h);
    sts16(lo_addr, l);
}

__device__ __forceinline__ void ldsm_x4(uint32_t* r, uint32_t addr) {
    asm volatile("ldmatrix.sync.aligned.m8n8.x4.shared.b16 {%0,%1,%2,%3}, [%4];"
                 : "=r"(r[0]), "=r"(r[1]), "=r"(r[2]), "=r"(r[3]) : "r"(addr));
}

__device__ __forceinline__ void mma_bf16(float* d, const uint32_t* a, uint32_t b0, uint32_t b1) {
    asm volatile(
        "mma.sync.aligned.m16n8k16.row.col.f32.bf16.bf16.f32 "
        "{%0,%1,%2,%3}, {%4,%5,%6,%7}, {%8,%9}, {%0,%1,%2,%3};"
        : "+f"(d[0]), "+f"(d[1]), "+f"(d[2]), "+f"(d[3])
        : "r"(a[0]), "r"(a[1]), "r"(a[2]), "r"(a[3]), "r"(b0), "r"(b1));
}

__global__ __launch_bounds__(THREADS, 2)
void moe_gemm_mma4_kernel(const float* __restrict__ inp,     // [T, D_IN]
                          const float* __restrict__ weight,  // [E, D_OUT, D_IN]
                          const float* __restrict__ bias,    // [E, D_OUT]
                          const int*   __restrict__ cnt,     // [E]
                          float*       __restrict__ out)     // [T, D_OUT]
{
    extern __shared__ char smem[];
    const uint32_t sbase = smem_u32_of(smem);

    const int tid = threadIdx.x;
    const int wid = tid >> 5;
    const int lid = tid & 31;

    const int nBase = blockIdx.x * BN;
    const int mBase = blockIdx.y * BM;

    int e = 0;
    {
        int acc = 0;
        #pragma unroll
        for (int i = 0; i < NUM_E; i++) {
            int c = cnt[i];
            if (mBase >= acc + c) { acc += c; e = i + 1; }
        }
    }
    const float* wptr = weight + (size_t)e * D_OUT * D_IN;

    // Warp layout: 2 (M) x 4 (N); warp tile 64x32
    const int warp_m = (wid >> 2) * 64;
    const int warp_n = (wid & 3) * 32;

    const int a_row = (lid & 7) + ((lid >> 3) & 1) * 8;
    const int a_ks  = ((lid >> 4) & 1) * 8;
    const int b_row = (lid & 7) + ((lid >> 4) & 1) * 8;
    const int b_ks  = ((lid >> 3) & 1) * 8;

    // Global staging: A/B each 128 rows x 16 fp32 -> 2 float4 per thread
    const int arow = tid >> 1;
    const int acol = (tid & 1) * 8;
    const float* aG = inp  + (size_t)(mBase + arow) * D_IN + acol;
    const float* bG = wptr + (size_t)(nBase + arow) * D_IN + acol;
    const uint32_t st_off = (uint32_t)(arow * ROW_B + acol * 2);

    float d[4][4][4];
    #pragma unroll
    for (int f = 0; f < 4; f++)
        #pragma unroll
        for (int n = 0; n < 4; n++)
            #pragma unroll
            for (int k = 0; k < 4; k++)
                d[f][n][k] = 0.0f;

    float aV[8], bV[8];

    #pragma unroll
    for (int q = 0; q < 2; q++) {
        *reinterpret_cast<float4*>(aV + q * 4) = *reinterpret_cast<const float4*>(aG + q * 4);
        *reinterpret_cast<float4*>(bV + q * 4) = *reinterpret_cast<const float4*>(bG + q * 4);
    }
    split_store8(aV, sbase + A_HI + st_off, sbase + A_LO + st_off);
    split_store8(bV, sbase + B_HI + st_off, sbase + B_LO + st_off);
    __syncthreads();

    for (int i = 0; i < NCHUNK; i++) {
        if (i + 1 < NCHUNK) {
            const int kb = (i + 1) * BK;
            #pragma unroll
            for (int q = 0; q < 2; q++) {
                *reinterpret_cast<float4*>(aV + q * 4) = *reinterpret_cast<const float4*>(aG + kb + q * 4);
                *reinterpret_cast<float4*>(bV + q * 4) = *reinterpret_cast<const float4*>(bG + kb + q * 4);
            }
        }

        const uint32_t cur = sbase + (uint32_t)(i & 1) * STAGE_B;

        // B fragments (hi and lo both resident: 16 regs)
        uint32_t bh[2][4], bl[2][4];
        #pragma unroll
        for (int nb = 0; nb < 2; nb++) {
            uint32_t ro = (uint32_t)((warp_n + nb * 16 + b_row) * ROW_B + b_ks * 2);
            ldsm_x4(bh[nb], cur + B_HI + ro);
            ldsm_x4(bl[nb], cur + B_LO + ro);
        }

        // Phase 1+2: A-hi fragments; terms hh and hl
        {
            uint32_t af[4][4];
            #pragma unroll
            for (int f = 0; f < 4; f++) {
                uint32_t ro = (uint32_t)((warp_m + f * 16 + a_row) * ROW_B + a_ks * 2);
                ldsm_x4(af[f], cur + A_HI + ro);
            }
            #pragma unroll
            for (int f = 0; f < 4; f++)
                #pragma unroll
                for (int nb = 0; nb < 2; nb++) {
                    mma_bf16(d[f][nb * 2 + 0], af[f], bh[nb][0], bh[nb][1]);
                    mma_bf16(d[f][nb * 2 + 1], af[f], bh[nb][2], bh[nb][3]);
                }
            #pragma unroll
            for (int f = 0; f < 4; f++)
                #pragma unroll
                for (int nb = 0; nb < 2; nb++) {
                    mma_bf16(d[f][nb * 2 + 0], af[f], bl[nb][0], bl[nb][1]);
                    mma_bf16(d[f][nb * 2 + 1], af[f], bl[nb][2], bl[nb][3]);
                }
        }
        // Phase 3: A-lo fragments (reuse registers); term lh
        {
            uint32_t af[4][4];
            #pragma unroll
            for (int f = 0; f < 4; f++) {
                uint32_t ro = (uint32_t)((warp_m + f * 16 + a_row) * ROW_B + a_ks * 2);
                ldsm_x4(af[f], cur + A_LO + ro);
            }
            #pragma unroll
            for (int f = 0; f < 4; f++)
                #pragma unroll
                for (int nb = 0; nb < 2; nb++) {
                    mma_bf16(d[f][nb * 2 + 0], af[f], bh[nb][0], bh[nb][1]);
                    mma_bf16(d[f][nb * 2 + 1], af[f], bh[nb][2], bh[nb][3]);
                }
        }

        if (i + 1 < NCHUNK) {
            const uint32_t nxt = sbase + (uint32_t)((i + 1) & 1) * STAGE_B;
            split_store8(aV, nxt + A_HI + st_off, nxt + A_LO + st_off);
            split_store8(bV, nxt + B_HI + st_off, nxt + B_LO + st_off);
        }
        __syncthreads();
    }

    const int g  = lid >> 2;
    const int t4 = lid & 3;
    const float* brow = bias + (size_t)e * D_OUT;
    #pragma unroll
    for (int f = 0; f < 4; f++) {
        const int row0 = mBase + warp_m + f * 16 + g;
        #pragma unroll
        for (int nf = 0; nf < 4; nf++) {
            const int col = nBase + warp_n + nf * 8 + t4 * 2;
            float2 bv = *reinterpret_cast<const float2*>(brow + col);
            float2 o0, o1;
            o0.x = d[f][nf][0] + bv.x;
            o0.y = d[f][nf][1] + bv.y;
            o1.x = d[f][nf][2] + bv.x;
            o1.y = d[f][nf][3] + bv.y;
            *reinterpret_cast<float2*>(out + (size_t)row0 * D_OUT + col) = o0;
            *reinterpret_cast<float2*>(out + (size_t)(row0 + 8) * D_OUT + col) = o1;
        }
    }
}

extern "C" void kernel_launch(void* const* d_in, const int* in_sizes, int n_in,
                              void* d_out, int out_size)
{
    const float* inp    = (const float*)d_in[0];
    const float* weight = (const float*)d_in[1];
    const float* bias   = (const float*)d_in[2];
    const int*   cnt    = (const int*)d_in[3];
    float* out = (float*)d_out;

    cudaFuncSetAttribute(moe_gemm_mma4_kernel,
                         cudaFuncAttributeMaxDynamicSharedMemorySize, SMEM_BYTES);

    dim3 grid(D_OUT / BN, T_TOK / BM);   // (64, 64)
    moe_gemm_mma4_kernel<<<grid, THREADS, SMEM_BYTES>>>(inp, weight, bias, cnt, out);
}

// round 7
// speedup vs baseline: 1.3543x; 1.1181x over previous
#include <cuda_runtime.h>
#include <cuda_bf16.h>
#include <cstdint>

#define NUM_E 16
#define D_IN  2048
#define D_OUT 8192
#define T_TOK 8192

// CTA tile 128(M) x 128(N), K-chunk 32 (2 k16 steps). 8 warps = 2(M) x 4(N),
// warp tile 64x32. Double-buffered smem, 2 CTAs/SM.
#define BM 128
#define BN 128
#define BK 32
#define NCHUNK (D_IN / BK)   // 64
#define THREADS 256

// Packed smem: per k16-half region = 128 rows x 32B (4KB), XOR-swizzled.
// Tile (hi or lo) = 2 halves = 8KB. Stage = A_hi,A_lo,B_hi,B_lo = 32KB.
#define REG_SZ  4096
#define A_HI    0
#define A_LO    8192
#define B_HI    16384
#define B_LO    24576
#define STAGE_B 32768
#define SMEM_BYTES (2 * STAGE_B)   // 65536

__device__ __forceinline__ uint32_t swz(uint32_t a) {
    return a ^ ((a & 128u) >> 3);   // flip 16B granule for rows 4-7 of each 8-row group
}

__device__ __forceinline__ uint32_t smem_u32_of(const void* p) {
    uint32_t a;
    asm("{ .reg .u64 t; cvta.to.shared.u64 t, %1; cvt.u32.u64 %0, t; }" : "=r"(a) : "l"(p));
    return a;
}

__device__ __forceinline__ uint32_t pack2(__nv_bfloat16 a, __nv_bfloat16 b) {
    __nv_bfloat162 t = __halves2bfloat162(a, b);
    return *reinterpret_cast<uint32_t*>(&t);
}

__device__ __forceinline__ void sts8(uint32_t addr, uint32_t x, uint32_t y) {
    asm volatile("st.shared.v2.b32 [%0], {%1, %2};" :: "r"(addr), "r"(x), "r"(y) : "memory");
}

// Split one float4 (4 consecutive k) into 8B hi + 8B lo and store.
__device__ __forceinline__ void split_store4(float4 v, uint32_t hi_addr, uint32_t lo_addr) {
    __nv_bfloat16 h0 = __float2bfloat16(v.x);
    __nv_bfloat16 h1 = __float2bfloat16(v.y);
    __nv_bfloat16 h2 = __float2bfloat16(v.z);
    __nv_bfloat16 h3 = __float2bfloat16(v.w);
    __nv_bfloat16 l0 = __float2bfloat16(v.x - __bfloat162float(h0));
    __nv_bfloat16 l1 = __float2bfloat16(v.y - __bfloat162float(h1));
    __nv_bfloat16 l2 = __float2bfloat16(v.z - __bfloat162float(h2));
    __nv_bfloat16 l3 = __float2bfloat16(v.w - __bfloat162float(h3));
    sts8(hi_addr, pack2(h0, h1), pack2(h2, h3));
    sts8(lo_addr, pack2(l0, l1), pack2(l2, l3));
}

__device__ __forceinline__ void ldsm_x4(uint32_t* r, uint32_t addr) {
    asm volatile("ldmatrix.sync.aligned.m8n8.x4.shared.b16 {%0,%1,%2,%3}, [%4];"
                 : "=r"(r[0]), "=r"(r[1]), "=r"(r[2]), "=r"(r[3]) : "r"(addr));
}

__device__ __forceinline__ void mma_bf16(float* d, const uint32_t* a, uint32_t b0, uint32_t b1) {
    asm volatile(
        "mma.sync.aligned.m16n8k16.row.col.f32.bf16.bf16.f32 "
        "{%0,%1,%2,%3}, {%4,%5,%6,%7}, {%8,%9}, {%0,%1,%2,%3};"
        : "+f"(d[0]), "+f"(d[1]), "+f"(d[2]), "+f"(d[3])
        : "r"(a[0]), "r"(a[1]), "r"(a[2]), "r"(a[3]), "r"(b0), "r"(b1));
}

__global__ __launch_bounds__(THREADS, 2)
void moe_gemm_mma5_kernel(const float* __restrict__ inp,     // [T, D_IN]
                          const float* __restrict__ weight,  // [E, D_OUT, D_IN]
                          const float* __restrict__ bias,    // [E, D_OUT]
                          const int*   __restrict__ cnt,     // [E]
                          float*       __restrict__ out)     // [T, D_OUT]
{
    extern __shared__ char smem[];
    const uint32_t sbase = smem_u32_of(smem);

    const int tid = threadIdx.x;
    const int wid = tid >> 5;
    const int lid = tid & 31;

    const int nBase = blockIdx.x * BN;
    const int mBase = blockIdx.y * BM;

    int e = 0;
    {
        int acc = 0;
        #pragma unroll
        for (int i = 0; i < NUM_E; i++) {
            int c = cnt[i];
            if (mBase >= acc + c) { acc += c; e = i + 1; }
        }
    }
    const float* wptr = weight + (size_t)e * D_OUT * D_IN;

    const int warp_m = (wid >> 2) * 64;
    const int warp_n = (wid & 3) * 32;

    // ldmatrix lane addressing (verified rounds 3-6)
    const int a_row = (lid & 7) + ((lid >> 3) & 1) * 8;
    const int a_c2  = (lid >> 4) & 1;          // k16-half granule (0 or 1)
    const int b_row = (lid & 7) + ((lid >> 4) & 1) * 8;
    const int b_c2  = (lid >> 3) & 1;

    // Coalesced staging: warp covers 4 rows x 128B per LDG.128 round.
    // thread: row_base = wid*4 + (lid>>3) (+ round*32), kq = lid&7 (fp32 quad).
    const int row_base = wid * 4 + (lid >> 3);
    const int kq = lid & 7;
    const uint32_t piece = swz((uint32_t)(row_base * 32 + (kq & 3) * 8));
    const uint32_t half_off = (uint32_t)((kq >> 2) * REG_SZ);

    const float* aG = inp  + (size_t)(mBase + row_base) * D_IN + kq * 4;
    const float* bG = wptr + (size_t)(nBase + row_base) * D_IN + kq * 4;

    float d[4][4][4];
    #pragma unroll
    for (int f = 0; f < 4; f++)
        #pragma unroll
        for (int n = 0; n < 4; n++)
            #pragma unroll
            for (int k = 0; k < 4; k++)
                d[f][n][k] = 0.0f;

    // ---- prologue: chunk 0 into stage 0 ----
    {
        float4 aS[4], bS[4];
        #pragma unroll
        for (int r = 0; r < 4; r++) {
            aS[r] = *reinterpret_cast<const float4*>(aG + (size_t)(r * 32) * D_IN);
            bS[r] = *reinterpret_cast<const float4*>(bG + (size_t)(r * 32) * D_IN);
        }
        #pragma unroll
        for (int r = 0; r < 4; r++) {
            uint32_t off = half_off + piece + (uint32_t)(r * 32 * 32);
            split_store4(aS[r], sbase + A_HI + off, sbase + A_LO + off);
            split_store4(bS[r], sbase + B_HI + off, sbase + B_LO + off);
        }
    }
    __syncthreads();

    #pragma unroll 1
    for (int i = 0; i < NCHUNK; i++) {
        const uint32_t cur = sbase + (uint32_t)(i & 1) * STAGE_B;
        const uint32_t nxt = sbase + (uint32_t)((i + 1) & 1) * STAGE_B;
        const bool pf = (i + 1 < NCHUNK);
        const int kb = (i + 1) * BK;

        float4 aS[4];
        if (pf) {
            #pragma unroll
            for (int r = 0; r < 4; r++)
                aS[r] = *reinterpret_cast<const float4*>(aG + kb + (size_t)(r * 32) * D_IN);
        }

        // ---- k16 step 0 ----
        {
            const uint32_t hb = cur;     // half 0
            uint32_t bh[2][4], bl[2][4];
            #pragma unroll
            for (int nb = 0; nb < 2; nb++) {
                uint32_t a = swz((uint32_t)((warp_n + nb * 16 + b_row) * 32 + b_c2 * 16));
                ldsm_x4(bh[nb], hb + B_HI + a);
                ldsm_x4(bl[nb], hb + B_LO + a);
            }
            {
                uint32_t af[4][4];
                #pragma unroll
                for (int f = 0; f < 4; f++) {
                    uint32_t a = swz((uint32_t)((warp_m + f * 16 + a_row) * 32 + a_c2 * 16));
                    ldsm_x4(af[f], hb + A_HI + a);
                }
                #pragma unroll
                for (int f = 0; f < 4; f++)
                    #pragma unroll
                    for (int nb = 0; nb < 2; nb++) {
                        mma_bf16(d[f][nb * 2 + 0], af[f], bh[nb][0], bh[nb][1]);
                        mma_bf16(d[f][nb * 2 + 1], af[f], bh[nb][2], bh[nb][3]);
                    }
                #pragma unroll
                for (int f = 0; f < 4; f++)
                    #pragma unroll
                    for (int nb = 0; nb < 2; nb++) {
                        mma_bf16(d[f][nb * 2 + 0], af[f], bl[nb][0], bl[nb][1]);
                        mma_bf16(d[f][nb * 2 + 1], af[f], bl[nb][2], bl[nb][3]);
                    }
            }
            {
                uint32_t af[4][4];
                #pragma unroll
                for (int f = 0; f < 4; f++) {
                    uint32_t a = swz((uint32_t)((warp_m + f * 16 + a_row) * 32 + a_c2 * 16));
                    ldsm_x4(af[f], hb + A_LO + a);
                }
                #pragma unroll
                for (int f = 0; f < 4; f++)
                    #pragma unroll
                    for (int nb = 0; nb < 2; nb++) {
                        mma_bf16(d[f][nb * 2 + 0], af[f], bh[nb][0], bh[nb][1]);
                        mma_bf16(d[f][nb * 2 + 1], af[f], bh[nb][2], bh[nb][3]);
                    }
            }
        }

        // store prefetched A, then load B for next chunk
        float4 bS[4];
        if (pf) {
            #pragma unroll
            for (int r = 0; r < 4; r++) {
                uint32_t off = half_off + piece + (uint32_t)(r * 32 * 32);
                split_store4(aS[r], nxt + A_HI + off, nxt + A_LO + off);
            }
            #pragma unroll
            for (int r = 0; r < 4; r++)
                bS[r] = *reinterpret_cast<const float4*>(bG + kb + (size_t)(r * 32) * D_IN);
        }

        // ---- k16 step 1 ----
        {
            const uint32_t hb = cur + REG_SZ;   // half 1
            uint32_t bh[2][4], bl[2][4];
            #pragma unroll
            for (int nb = 0; nb < 2; nb++) {
                uint32_t a = swz((uint32_t)((warp_n + nb * 16 + b_row) * 32 + b_c2 * 16));
                ldsm_x4(bh[nb], hb + B_HI + a);
                ldsm_x4(bl[nb], hb + B_LO + a);
            }
            {
                uint32_t af[4][4];
                #pragma unroll
                for (int f = 0; f < 4; f++) {
                    uint32_t a = swz((uint32_t)((warp_m + f * 16 + a_row) * 32 + a_c2 * 16));
                    ldsm_x4(af[f], hb + A_HI + a);
                }
                #pragma unroll
                for (int f = 0; f < 4; f++)
                    #pragma unroll
                    for (int nb = 0; nb < 2; nb++) {
                        mma_bf16(d[f][nb * 2 + 0], af[f], bh[nb][0], bh[nb][1]);
                        mma_bf16(d[f][nb * 2 + 1], af[f], bh[nb][2], bh[nb][3]);
                    }
                #pragma unroll
                for (int f = 0; f < 4; f++)
                    #pragma unroll
                    for (int nb = 0; nb < 2; nb++) {
                        mma_bf16(d[f][nb * 2 + 0], af[f], bl[nb][0], bl[nb][1]);
                        mma_bf16(d[f][nb * 2 + 1], af[f], bl[nb][2], bl[nb][3]);
                    }
            }
            {
                uint32_t af[4][4];
                #pragma unroll
                for (int f = 0; f < 4; f++) {
                    uint32_t a = swz((uint32_t)((warp_m + f * 16 + a_row) * 32 + a_c2 * 16));
                    ldsm_x4(af[f], hb + A_LO + a);
                }
                #pragma unroll
                for (int f = 0; f < 4; f++)
                    #pragma unroll
                    for (int nb = 0; nb < 2; nb++) {
                        mma_bf16(d[f][nb * 2 + 0], af[f], bh[nb][0], bh[nb][1]);
                        mma_bf16(d[f][nb * 2 + 1], af[f], bh[nb][2], bh[nb][3]);
                    }
            }
        }

        if (pf) {
            #pragma unroll
            for (int r = 0; r < 4; r++) {
                uint32_t off = half_off + piece + (uint32_t)(r * 32 * 32);
                split_store4(bS[r], nxt + B_HI + off, nxt + B_LO + off);
            }
        }
        __syncthreads();
    }

    // ---- epilogue: bias + fp32 store ----
    const int g  = lid >> 2;
    const int t4 = lid & 3;
    const float* brow = bias + (size_t)e * D_OUT;
    #pragma unroll
    for (int f = 0; f < 4; f++) {
        const int row0 = mBase + warp_m + f * 16 + g;
        #pragma unroll
        for (int nf = 0; nf < 4; nf++) {
            const int col = nBase + warp_n + nf * 8 + t4 * 2;
            float2 bv = *reinterpret_cast<const float2*>(brow + col);
            float2 o0, o1;
            o0.x = d[f][nf][0] + bv.x;
            o0.y = d[f][nf][1] + bv.y;
            o1.x = d[f][nf][2] + bv.x;
            o1.y = d[f][nf][3] + bv.y;
            *reinterpret_cast<float2*>(out + (size_t)row0 * D_OUT + col) = o0;
            *reinterpret_cast<float2*>(out + (size_t)(row0 + 8) * D_OUT + col) = o1;
        }
    }
}

extern "C" void kernel_launch(void* const* d_in, const int* in_sizes, int n_in,
                              void* d_out, int out_size)
{
    const float* inp    = (const float*)d_in[0];
    const float* weight = (const float*)d_in[1];
    const float* bias   = (const float*)d_in[2];
    const int*   cnt    = (const int*)d_in[3];
    float* out = (float*)d_out;

    cudaFuncSetAttribute(moe_gemm_mma5_kernel,
                         cudaFuncAttributeMaxDynamicSharedMemorySize, SMEM_BYTES);

    dim3 grid(D_OUT / BN, T_TOK / BM);   // (64, 64)
    moe_gemm_mma5_kernel<<<grid, THREADS, SMEM_BYTES>>>(inp, weight, bias, cnt, out);
}